// round 16
// baseline (speedup 1.0000x reference)
#include <cuda_runtime.h>
#include <cuda_bf16.h>
#include <math.h>

#define NN 20000
#define EE 320000
#define ET (EE + NN)
#define FIN 128
#define F2C 64
#define HC 8
#define D1 512
#define G4 256

// ---------------- scratch ----------------------------------------------------
__device__ float g_v1[FIN * 16];
__device__ float g_v2[F2C * 16];
__device__ __nv_bfloat16 g_W1b[D1 * FIN];
__device__ __nv_bfloat16 g_Wihb[G4 * D1];
__device__ __nv_bfloat16 g_W2b[D1 * F2C];
__device__ __nv_bfloat16 g_h1b[NN * D1];
__device__ __nv_bfloat16 g_agg1b[NN * D1];
__device__ float g_gates[NN * G4];
__device__ __nv_bfloat16 g_h2b[NN * F2C];
__device__ __nv_bfloat16 g_h3b[NN * D1];
__device__ float g_as[NN * HC];
__device__ float g_ad[NN * HC];
__device__ int   g_deg[NN];
__device__ int   g_offs[NN + 1];
__device__ int   g_cur[NN];
__device__ int   g_csrc[ET];

__device__ __forceinline__ float sigf(float x) { return 1.0f / (1.0f + __expf(-x)); }
__device__ __forceinline__ float lrelu(float e) { return (e > 0.f) ? e : 0.2f * e; }
__device__ __forceinline__ unsigned packbf(float a, float b) {
    __nv_bfloat162 t = __floats2bfloat162_rn(a, b);
    return *(unsigned*)&t;
}

// ---------------- CSR build ----------------------------------------------------
__global__ void k_degree(const int* __restrict__ ei, int E) {
    int i = blockIdx.x * blockDim.x + threadIdx.x;
    if (i >= E + NN) return;
    int dst = (i < E) ? ei[E + i] : (i - E);
    atomicAdd(&g_deg[dst], 1);
}

__global__ void k_scan() {
    __shared__ int sums[1024];
    const int CH = 20;
    int t = threadIdx.x;
    int b = t * CH;
    int e = min(b + CH, NN);
    int tmp[CH];
    int local = 0;
    for (int i = b; i < e; i++) { tmp[i - b] = g_deg[i]; local += tmp[i - b]; }
    sums[t] = local;
    __syncthreads();
    for (int o = 1; o < 1024; o <<= 1) {
        int v = (t >= o) ? sums[t - o] : 0;
        __syncthreads();
        sums[t] += v;
        __syncthreads();
    }
    int run = sums[t] - local;
    for (int i = b; i < e; i++) {
        g_offs[i] = run;
        g_cur[i]  = run;
        run += tmp[i - b];
    }
    if (b < NN && e == NN) g_offs[NN] = run;
}

__global__ void k_scatter(const int* __restrict__ ei, int E) {
    int i = blockIdx.x * blockDim.x + threadIdx.x;
    if (i >= E + NN) return;
    int src, dst;
    if (i < E) { src = ei[i]; dst = ei[E + i]; }
    else       { src = dst = i - E; }
    int pos = atomicAdd(&g_cur[dst], 1);
    g_csrc[pos] = src;
}

// ---------------- weight prep ----------------------------------------------------
__global__ void k_prepw(const float* __restrict__ W1, const float* __restrict__ Wih,
                        const float* __restrict__ W2) {
    int idx = blockIdx.x * blockDim.x + threadIdx.x;
    const int S0 = FIN * D1;
    const int S1 = G4 * D1;
    const int S2 = F2C * D1;
    if (idx < S0) {
        int r = idx / D1, c = idx % D1;
        g_W1b[(long)c * FIN + r] = __float2bfloat16(W1[idx]);
    } else if (idx < S0 + S1) {
        int i = idx - S0;
        g_Wihb[i] = __float2bfloat16(Wih[i]);
    } else if (idx < S0 + S1 + S2) {
        int i = idx - S0 - S1;
        int r = i / D1, c = i % D1;
        g_W2b[(long)c * F2C + r] = __float2bfloat16(W2[i]);
    }
}

__global__ void k_folds(const float* __restrict__ W1, const float* __restrict__ as1,
                        const float* __restrict__ ad1,
                        const float* __restrict__ W2, const float* __restrict__ as2,
                        const float* __restrict__ ad2) {
    int idx = blockIdx.x * blockDim.x + threadIdx.x;
    const int N1 = FIN * 16;
    const int N2 = F2C * 16;
    const float* W; const float* asv; const float* adv; float* V; int li;
    if (idx < N1) { W = W1; asv = as1; adv = ad1; V = g_v1; li = idx; }
    else if (idx < N1 + N2) { W = W2; asv = as2; adv = ad2; V = g_v2; li = idx - N1; }
    else return;
    int k = li >> 4;
    int col = li & 15;
    int h = col & 7;
    const float* att = (col & 8) ? adv : asv;
    float acc = 0.f;
#pragma unroll 8
    for (int f = 0; f < F2C; f++)
        acc += W[(long)k * D1 + h * F2C + f] * att[h * F2C + f];
    V[li] = acc;
}

// ---------------- attention logits layer 1 (from x) ------------------------------
template <int K>
__global__ __launch_bounds__(256) void k_attnx(const float* __restrict__ feat,
                                               const float* __restrict__ V) {
    __shared__ float sV[K * 17];
    int tid = threadIdx.x;
    for (int idx = tid; idx < K * 16; idx += 256) {
        int k = idx >> 4, c = idx & 15;
        sV[k * 17 + c] = V[idx];
    }
    __syncthreads();
    int warp = tid >> 5, lane = tid & 31;
    int n = blockIdx.x * 8 + warp;
    if (n >= NN) return;
    float xv[K / 32];
#pragma unroll
    for (int c = 0; c < K / 32; c++) xv[c] = feat[(long)n * K + c * 32 + lane];
    float acc[16];
#pragma unroll
    for (int h = 0; h < 16; h++) acc[h] = 0.f;
#pragma unroll
    for (int c = 0; c < K / 32; c++) {
        int k = c * 32 + lane;
#pragma unroll
        for (int h = 0; h < 16; h++) acc[h] += xv[c] * sV[k * 17 + h];
    }
#pragma unroll
    for (int off = 16; off > 0; off >>= 1)
#pragma unroll
        for (int h = 0; h < 16; h++)
            acc[h] += __shfl_xor_sync(0xffffffffu, acc[h], off);
    if (lane == 0) {
#pragma unroll
        for (int h = 0; h < 8; h++) {
            g_as[n * HC + h] = acc[h];
            g_ad[n * HC + h] = acc[8 + h];
        }
    }
}

// ---------------- fused aggregation (R13/R15-proven) -------------------------------
template <typename TO, bool SMAX>
__global__ __launch_bounds__(128) void k_agg(const __nv_bfloat16* __restrict__ hsrc,
                                             const float* __restrict__ bias,
                                             TO* __restrict__ out) {
    __shared__ float sAl[32][9];
    __shared__ int   sSrc[32];
    __shared__ float sMx[8], sInv[8], sAd[8];
    __shared__ float red[128];
    int n = blockIdx.x;
    int t = threadIdx.x;
    int h = t >> 4, sub = t & 15;
    int beg = g_offs[n], end = g_offs[n + 1];
    int deg = end - beg;
    if (t < 8) sAd[t] = g_ad[n * HC + t];
    __syncthreads();

    float4 acc = make_float4(0.f, 0.f, 0.f, 0.f);
    float inv;

    if (deg <= 32) {
        int cnt = deg;
        for (int v = t; v < cnt * 8; v += 128) {
            int c = v >> 3, hh = v & 7;
            int src = g_csrc[beg + c];
            if (hh == 0) sSrc[c] = src;
            sAl[c][hh] = lrelu(g_as[src * HC + hh] + sAd[hh]);
        }
        __syncthreads();
        float mx = -1e30f, s = 0.f;
        for (int c = sub; c < cnt; c += 16) {
            float e = sAl[c][h];
            float nm = fmaxf(mx, e);
            s = s * __expf(mx - nm) + __expf(e - nm);
            mx = nm;
        }
#pragma unroll
        for (int o = 8; o > 0; o >>= 1) {
            float mo = __shfl_xor_sync(0xffffffffu, mx, o, 16);
            float so = __shfl_xor_sync(0xffffffffu, s, o, 16);
            float nm = fmaxf(mx, mo);
            s = s * __expf(mx - nm) + so * __expf(mo - nm);
            mx = nm;
        }
        if (sub == 0) {
            sMx[h] = mx;
            sInv[h] = 1.0f / (s + 1e-16f);
        }
        __syncthreads();
        for (int v = t; v < cnt * 8; v += 128) {
            int c = v >> 3, hh = v & 7;
            sAl[c][hh] = __expf(sAl[c][hh] - sMx[hh]);
        }
        __syncthreads();
        inv = sInv[h];
        for (int c = 0; c < cnt; c++) {
            float alpha = sAl[c][h];
            int src = sSrc[c];
            uint2 u = *(const uint2*)&hsrc[(long)src * D1 + t * 4];
            float2 p0 = __bfloat1622float2(*(__nv_bfloat162*)&u.x);
            float2 p1 = __bfloat1622float2(*(__nv_bfloat162*)&u.y);
            acc.x += alpha * p0.x;
            acc.y += alpha * p0.y;
            acc.z += alpha * p1.x;
            acc.w += alpha * p1.y;
        }
    } else {
        float mx = -1e30f, s = 0.f;
        float adn = sAd[h];
        for (int j = beg + sub; j < end; j += 16) {
            float e = lrelu(g_as[g_csrc[j] * HC + h] + adn);
            float nm = fmaxf(mx, e);
            s = s * __expf(mx - nm) + __expf(e - nm);
            mx = nm;
        }
#pragma unroll
        for (int o = 8; o > 0; o >>= 1) {
            float mo = __shfl_xor_sync(0xffffffffu, mx, o, 16);
            float so = __shfl_xor_sync(0xffffffffu, s, o, 16);
            float nm = fmaxf(mx, mo);
            s = s * __expf(mx - nm) + so * __expf(mo - nm);
            mx = nm;
        }
        if (sub == 0) {
            sMx[h] = mx;
            sInv[h] = 1.0f / (s + 1e-16f);
        }
        __syncthreads();
        inv = sInv[h];
        for (int c0 = beg; c0 < end; c0 += 32) {
            int cnt = min(32, end - c0);
            __syncthreads();
            for (int v = t; v < cnt * 8; v += 128) {
                int c = v >> 3, hh = v & 7;
                int src = g_csrc[c0 + c];
                if (hh == 0) sSrc[c] = src;
                float e = lrelu(g_as[src * HC + hh] + sAd[hh]);
                sAl[c][hh] = __expf(e - sMx[hh]);
            }
            __syncthreads();
            for (int c = 0; c < cnt; c++) {
                float alpha = sAl[c][h];
                int src = sSrc[c];
                uint2 u = *(const uint2*)&hsrc[(long)src * D1 + t * 4];
                float2 p0 = __bfloat1622float2(*(__nv_bfloat162*)&u.x);
                float2 p1 = __bfloat1622float2(*(__nv_bfloat162*)&u.y);
                acc.x += alpha * p0.x;
                acc.y += alpha * p0.y;
                acc.z += alpha * p1.x;
                acc.w += alpha * p1.y;
            }
        }
    }

    float4 b = *(const float4*)&bias[t * 4];
    acc.x = acc.x * inv + b.x;
    acc.y = acc.y * inv + b.y;
    acc.z = acc.z * inv + b.z;
    acc.w = acc.w * inv + b.w;

    if (!SMAX) {
        if (sizeof(TO) == 2) {
            uint2 u = make_uint2(packbf(acc.x, acc.y), packbf(acc.z, acc.w));
            *(uint2*)&out[(long)n * D1 + t * 4] = u;
        } else {
            *(float4*)&((float*)out)[(long)n * D1 + t * 4] = acc;
        }
        return;
    }

    float lm = fmaxf(fmaxf(acc.x, acc.y), fmaxf(acc.z, acc.w));
    red[t] = lm;
    __syncthreads();
#pragma unroll
    for (int o = 64; o > 0; o >>= 1) {
        if (t < o) red[t] = fmaxf(red[t], red[t + o]);
        __syncthreads();
    }
    float gm = red[0];
    __syncthreads();
    float e0 = __expf(acc.x - gm), e1 = __expf(acc.y - gm);
    float e2 = __expf(acc.z - gm), e3 = __expf(acc.w - gm);
    red[t] = e0 + e1 + e2 + e3;
    __syncthreads();
#pragma unroll
    for (int o = 64; o > 0; o >>= 1) {
        if (t < o) red[t] += red[t + o];
        __syncthreads();
    }
    float rinv = 1.0f / red[0];
    float* fout = (float*)out;
    *(float4*)&fout[(long)n * D1 + t * 4] =
        make_float4(e0 * rinv, e1 * rinv, e2 * rinv, e3 * rinv);
}

// ---------------- bf16 TN GEMM: cp.async pipeline, compact SMEM stride --------------
// SROW=20 uints (80B): ldmatrix 8-row phase banks 20r mod 32 = {0,20,8,28,16,4,24,12}
// all distinct -> conflict-free; 40KB total -> 5 CTAs/SM.
#define SROW 20
#define ABYTES (128 * SROW * 4)
#define STAGEB (2 * ABYTES)
#define SMEMB  (2 * STAGEB)

template <typename TO>
__device__ __forceinline__ void storeC2(TO* C, long idx, float a, float b);
template <>
__device__ __forceinline__ void storeC2<float>(float* C, long idx, float a, float b) {
    *(float2*)&C[idx] = make_float2(a, b);
}
template <>
__device__ __forceinline__ void storeC2<__nv_bfloat16>(__nv_bfloat16* C, long idx, float a, float b) {
    unsigned u = packbf(a, b);
    *(unsigned*)&C[idx] = u;
}

__device__ __forceinline__ void ldsm4(unsigned& r0, unsigned& r1, unsigned& r2, unsigned& r3,
                                      unsigned addr) {
    asm volatile("ldmatrix.sync.aligned.m8n8.x4.shared.b16 {%0,%1,%2,%3}, [%4];"
                 : "=r"(r0), "=r"(r1), "=r"(r2), "=r"(r3) : "r"(addr));
}

__device__ __forceinline__ void cpasync16(unsigned dst, const void* src) {
    asm volatile("cp.async.cg.shared.global [%0], [%1], 16;" :: "r"(dst), "l"(src));
}

__device__ __forceinline__ void stsu4(unsigned addr, uint4 v) {
    asm volatile("st.shared.v4.b32 [%0], {%1,%2,%3,%4};"
                 :: "r"(addr), "r"(v.x), "r"(v.y), "r"(v.z), "r"(v.w));
}

template <typename TO, typename TI>
__global__ __launch_bounds__(256) void k_bgemm(int M, int N, int K,
                                               const TI* __restrict__ A,
                                               const __nv_bfloat16* __restrict__ Bt,
                                               TO* __restrict__ C) {
    constexpr bool CVTA = (sizeof(TI) == 4);
    extern __shared__ unsigned char smemRaw[];
    unsigned sBase = (unsigned)__cvta_generic_to_shared(smemRaw);
    int tid  = threadIdx.x;
    int lane = tid & 31;
    int warp = tid >> 5;
    int wr = warp & 3;
    int wc = warp >> 2;
    int blockRow = blockIdx.y * 128;
    int blockCol = blockIdx.x * 128;

    float acc[2][8][4];
#pragma unroll
    for (int i = 0; i < 2; i++)
#pragma unroll
        for (int j = 0; j < 8; j++)
#pragma unroll
            for (int q = 0; q < 4; q++) acc[i][j][q] = 0.0f;

    int sub = lane >> 3;
    int l7  = lane & 7;
    unsigned aOff[2];
#pragma unroll
    for (int i = 0; i < 2; i++) {
        int row = wr * 32 + i * 16 + (sub & 1) * 8 + l7;
        aOff[i] = row * (SROW * 4) + (sub >> 1) * 16;
    }
    unsigned bOff[4];
#pragma unroll
    for (int jj = 0; jj < 4; jj++) {
        int tile = jj * 2 + (sub >> 1);
        int row = wc * 64 + tile * 8 + l7;
        bOff[jj] = ABYTES + row * (SROW * 4) + (sub & 1) * 16;
    }

    int sr[2], sc[2], arow[2];
#pragma unroll
    for (int i = 0; i < 2; i++) {
        int idx = tid + i * 256;
        sr[i] = idx >> 2;
        sc[i] = idx & 3;
        arow[i] = min(blockRow + sr[i], M - 1);
    }

    int nk = K / 32;
    float4 fa[2][2], fan[2][2];

#pragma unroll
    for (int i = 0; i < 2; i++) {
        if (CVTA) {
            const float* af = (const float*)A;
            fa[i][0] = *(const float4*)&af[(long)arow[i] * K + sc[i] * 8];
            fa[i][1] = *(const float4*)&af[(long)arow[i] * K + sc[i] * 8 + 4];
        } else {
            unsigned dA = sBase + (sr[i] * SROW + sc[i] * 4) * 4;
            cpasync16(dA, &((const __nv_bfloat16*)A)[(long)arow[i] * K + sc[i] * 8]);
        }
        unsigned dB = sBase + ABYTES + (sr[i] * SROW + sc[i] * 4) * 4;
        cpasync16(dB, &Bt[(long)(blockCol + sr[i]) * K + sc[i] * 8]);
    }
    asm volatile("cp.async.commit_group;" ::: "memory");

    for (int it = 0; it < nk; it++) {
        int stage = it & 1;
        if (CVTA) {
#pragma unroll
            for (int i = 0; i < 2; i++) {
                uint4 u = make_uint4(packbf(fa[i][0].x, fa[i][0].y),
                                     packbf(fa[i][0].z, fa[i][0].w),
                                     packbf(fa[i][1].x, fa[i][1].y),
                                     packbf(fa[i][1].z, fa[i][1].w));
                stsu4(sBase + stage * STAGEB + (sr[i] * SROW + sc[i] * 4) * 4, u);
            }
        }
        if (it + 1 < nk) {
            int nst = (it + 1) & 1;
            int koff = (it + 1) * 32;
#pragma unroll
            for (int i = 0; i < 2; i++) {
                if (CVTA) {
                    const float* af = (const float*)A;
                    fan[i][0] = *(const float4*)&af[(long)arow[i] * K + koff + sc[i] * 8];
                    fan[i][1] = *(const float4*)&af[(long)arow[i] * K + koff + sc[i] * 8 + 4];
                } else {
                    unsigned dA = sBase + nst * STAGEB + (sr[i] * SROW + sc[i] * 4) * 4;
                    cpasync16(dA, &((const __nv_bfloat16*)A)[(long)arow[i] * K + koff + sc[i] * 8]);
                }
                unsigned dB = sBase + nst * STAGEB + ABYTES + (sr[i] * SROW + sc[i] * 4) * 4;
                cpasync16(dB, &Bt[(long)(blockCol + sr[i]) * K + koff + sc[i] * 8]);
            }
            asm volatile("cp.async.commit_group;" ::: "memory");
            asm volatile("cp.async.wait_group 1;" ::: "memory");
        } else {
            asm volatile("cp.async.wait_group 0;" ::: "memory");
        }
        __syncthreads();

        unsigned stBase = sBase + stage * STAGEB;
#pragma unroll
        for (int ks = 0; ks < 2; ks++) {
            unsigned kadd = ks * 32;
            unsigned a[2][4], b[8][2];
#pragma unroll
            for (int i = 0; i < 2; i++)
                ldsm4(a[i][0], a[i][1], a[i][2], a[i][3], stBase + aOff[i] + kadd);
#pragma unroll
            for (int jj = 0; jj < 4; jj++)
                ldsm4(b[jj * 2][0], b[jj * 2][1], b[jj * 2 + 1][0], b[jj * 2 + 1][1],
                      stBase + bOff[jj] + kadd);
#pragma unroll
            for (int i = 0; i < 2; i++) {
#pragma unroll
                for (int j = 0; j < 8; j++) {
                    asm volatile(
                        "mma.sync.aligned.m16n8k16.row.col.f32.bf16.bf16.f32 "
                        "{%0,%1,%2,%3}, {%4,%5,%6,%7}, {%8,%9}, {%0,%1,%2,%3};"
                        : "+f"(acc[i][j][0]), "+f"(acc[i][j][1]),
                          "+f"(acc[i][j][2]), "+f"(acc[i][j][3])
                        : "r"(a[i][0]), "r"(a[i][1]), "r"(a[i][2]), "r"(a[i][3]),
                          "r"(b[j][0]), "r"(b[j][1]));
                }
            }
        }
        if (CVTA) {
#pragma unroll
            for (int i = 0; i < 2; i++) {
                fa[i][0] = fan[i][0];
                fa[i][1] = fan[i][1];
            }
        }
        __syncthreads();
    }

#pragma unroll
    for (int i = 0; i < 2; i++) {
        int r = blockRow + wr * 32 + i * 16 + (lane >> 2);
#pragma unroll
        for (int j = 0; j < 8; j++) {
            int c = blockCol + wc * 64 + j * 8 + (lane & 3) * 2;
            if (r < M)
                storeC2<TO>(C, (long)r * N + c, acc[i][j][0], acc[i][j][1]);
            if (r + 8 < M)
                storeC2<TO>(C, (long)(r + 8) * N + c, acc[i][j][2], acc[i][j][3]);
        }
    }
}

// ---------------- LSTM + fused layer-2 attention logits ------------------------------
__global__ __launch_bounds__(256) void k_lstm(const float* __restrict__ b_ih,
                                              const float* __restrict__ b_hh,
                                              const float* __restrict__ V2) {
    __shared__ float sV[F2C * 17];
    __shared__ float sH[4][F2C];
    int t = threadIdx.x;
    for (int idx = t; idx < F2C * 16; idx += 256) {
        int k = idx >> 4, c = idx & 15;
        sV[k * 17 + c] = V2[idx];
    }
    int nb = blockIdx.x * 4 + (t >> 6);
    int j = t & 63;
    float r = 0.f;
    if (nb < NN) {
        const float* g = g_gates + (long)nb * G4;
        float i_ = g[j]       + b_ih[j]       + b_hh[j];
        float gg = g[128 + j] + b_ih[128 + j] + b_hh[128 + j];
        float o_ = g[192 + j] + b_ih[192 + j] + b_hh[192 + j];
        float c  = sigf(i_) * tanhf(gg);
        r = fmaxf(sigf(o_) * tanhf(c), 0.0f);
        g_h2b[(long)nb * F2C + j] = __float2bfloat16(r);
    }
    sH[t >> 6][j] = r;
    __syncthreads();
    int p = t >> 2, q = t & 3;
    int node = p >> 4, c = p & 15;
    float sum = 0.f;
#pragma unroll
    for (int k = 0; k < 16; k++)
        sum += sH[node][q * 16 + k] * sV[(q * 16 + k) * 17 + c];
    sum += __shfl_xor_sync(0xffffffffu, sum, 1, 4);
    sum += __shfl_xor_sync(0xffffffffu, sum, 2, 4);
    if (q == 0) {
        int n2 = blockIdx.x * 4 + node;
        if (n2 < NN) {
            if (c < 8) g_as[n2 * HC + c] = sum;
            else       g_ad[n2 * HC + c - 8] = sum;
        }
    }
}

// ---------------- launch ------------------------------------------------------------------
extern "C" void kernel_launch(void* const* d_in, const int* in_sizes, int n_in,
                              void* d_out, int out_size) {
    const float* x        = (const float*)d_in[0];
    const int*   ei       = (const int*)d_in[1];
    const float* W1       = (const float*)d_in[3];
    const float* att_src1 = (const float*)d_in[4];
    const float* att_dst1 = (const float*)d_in[5];
    const float* bias1    = (const float*)d_in[6];
    const float* W_ih     = (const float*)d_in[7];
    const float* b_ih     = (const float*)d_in[9];
    const float* b_hh     = (const float*)d_in[10];
    const float* W2       = (const float*)d_in[11];
    const float* att_src2 = (const float*)d_in[12];
    const float* att_dst2 = (const float*)d_in[13];
    const float* bias2    = (const float*)d_in[14];
    float* out = (float*)d_out;

    int E = in_sizes[1] / 2;
    int etot = E + NN;

    void* p_deg = nullptr;   cudaGetSymbolAddress(&p_deg, g_deg);
    void* p_v1 = nullptr;    cudaGetSymbolAddress(&p_v1, g_v1);
    void* p_v2 = nullptr;    cudaGetSymbolAddress(&p_v2, g_v2);
    void* p_W1b = nullptr;   cudaGetSymbolAddress(&p_W1b, g_W1b);
    void* p_Wihb = nullptr;  cudaGetSymbolAddress(&p_Wihb, g_Wihb);
    void* p_W2b = nullptr;   cudaGetSymbolAddress(&p_W2b, g_W2b);
    void* p_h1b = nullptr;   cudaGetSymbolAddress(&p_h1b, g_h1b);
    void* p_agg1b = nullptr; cudaGetSymbolAddress(&p_agg1b, g_agg1b);
    void* p_gates = nullptr; cudaGetSymbolAddress(&p_gates, g_gates);
    void* p_h2b = nullptr;   cudaGetSymbolAddress(&p_h2b, g_h2b);
    void* p_h3b = nullptr;   cudaGetSymbolAddress(&p_h3b, g_h3b);

    static bool s_init = false;
    static cudaStream_t s1, s2;
    static cudaEvent_t evFork, evCsr, evPrepW, evAtt1;
    if (!s_init) {
        cudaFuncSetAttribute(k_bgemm<__nv_bfloat16, float>,
                             cudaFuncAttributeMaxDynamicSharedMemorySize, SMEMB);
        cudaFuncSetAttribute(k_bgemm<__nv_bfloat16, __nv_bfloat16>,
                             cudaFuncAttributeMaxDynamicSharedMemorySize, SMEMB);
        cudaFuncSetAttribute(k_bgemm<float, __nv_bfloat16>,
                             cudaFuncAttributeMaxDynamicSharedMemorySize, SMEMB);
        cudaStreamCreateWithFlags(&s1, cudaStreamNonBlocking);
        cudaStreamCreateWithFlags(&s2, cudaStreamNonBlocking);
        cudaEventCreateWithFlags(&evFork, cudaEventDisableTiming);
        cudaEventCreateWithFlags(&evCsr, cudaEventDisableTiming);
        cudaEventCreateWithFlags(&evPrepW, cudaEventDisableTiming);
        cudaEventCreateWithFlags(&evAtt1, cudaEventDisableTiming);
        s_init = true;
    }

    // ---- fork ----
    cudaEventRecord(evFork, 0);
    cudaStreamWaitEvent(s1, evFork, 0);
    cudaStreamWaitEvent(s2, evFork, 0);

    // s1: CSR chain
    cudaMemsetAsync(p_deg, 0, NN * sizeof(int), s1);
    k_degree<<<(etot + 255) / 256, 256, 0, s1>>>(ei, E);
    k_scan<<<1, 1024, 0, s1>>>();
    k_scatter<<<(etot + 255) / 256, 256, 0, s1>>>(ei, E);
    cudaEventRecord(evCsr, s1);

    // s2: weight prep -> folds -> attnx1
    k_prepw<<<((FIN + G4 + F2C) * D1 + 255) / 256, 256, 0, s2>>>(W1, W_ih, W2);
    cudaEventRecord(evPrepW, s2);
    k_folds<<<((FIN + F2C) * 16 + 255) / 256, 256, 0, s2>>>(W1, att_src1, att_dst1,
                                                            W2, att_src2, att_dst2);
    k_attnx<FIN><<<2500, 256, 0, s2>>>(x, (const float*)p_v1);
    cudaEventRecord(evAtt1, s2);

    // default stream: GEMM1 (fp32 x converted in-kernel)
    cudaStreamWaitEvent(0, evPrepW, 0);
    {
        dim3 grid(D1 / 128, (NN + 127) / 128);
        k_bgemm<__nv_bfloat16, float><<<grid, 256, SMEMB>>>(NN, D1, FIN, x,
                                                            (const __nv_bfloat16*)p_W1b,
                                                            (__nv_bfloat16*)p_h1b);
    }
    cudaStreamWaitEvent(0, evCsr, 0);
    cudaStreamWaitEvent(0, evAtt1, 0);

    // ---- layer 1 ----
    k_agg<__nv_bfloat16, false><<<NN, 128>>>((const __nv_bfloat16*)p_h1b, bias1,
                                             (__nv_bfloat16*)p_agg1b);
    {
        dim3 grid(G4 / 128, (NN + 127) / 128);
        k_bgemm<float, __nv_bfloat16><<<grid, 256, SMEMB>>>(NN, G4, D1,
                                                            (const __nv_bfloat16*)p_agg1b,
                                                            (const __nv_bfloat16*)p_Wihb,
                                                            (float*)p_gates);
    }
    // LSTM + fused layer-2 attention logits
    k_lstm<<<(NN + 3) / 4, 256>>>(b_ih, b_hh, (const float*)p_v2);

    // ---- layer 2 ----
    {
        dim3 grid(D1 / 128, (NN + 127) / 128);
        k_bgemm<__nv_bfloat16, __nv_bfloat16><<<grid, 256, SMEMB>>>(NN, D1, F2C,
                                                                    (const __nv_bfloat16*)p_h2b,
                                                                    (const __nv_bfloat16*)p_W2b,
                                                                    (__nv_bfloat16*)p_h3b);
    }
    // fused gather + bias2 + softmax -> out
    k_agg<float, true><<<NN, 128>>>((const __nv_bfloat16*)p_h3b, bias2, out);
}

// round 17
// speedup vs baseline: 1.0796x; 1.0796x over previous
#include <cuda_runtime.h>
#include <cuda_bf16.h>
#include <math.h>

#define NN 20000
#define EE 320000
#define ET (EE + NN)
#define FIN 128
#define F2C 64
#define HC 8
#define D1 512
#define G4 256
#define NHALF 10000

// ---------------- scratch ----------------------------------------------------
__device__ float g_v1[FIN * 16];
__device__ float g_v2[F2C * 16];
__device__ __nv_bfloat16 g_W1b[D1 * FIN];
__device__ __nv_bfloat16 g_Wihb[G4 * D1];
__device__ __nv_bfloat16 g_W2b[D1 * F2C];
__device__ __nv_bfloat16 g_h1b[NN * D1];
__device__ __nv_bfloat16 g_agg1b[NN * D1];
__device__ float g_gates[NN * G4];
__device__ __nv_bfloat16 g_h2b[NN * F2C];
__device__ __nv_bfloat16 g_h3b[NN * D1];
__device__ float g_as[NN * HC];     // layer-1 logits
__device__ float g_ad[NN * HC];
__device__ float g_as2[NN * HC];    // layer-2 logits (separate: chunk-race safety)
__device__ float g_ad2[NN * HC];
__device__ int   g_deg[NN];
__device__ int   g_offs[NN + 1];
__device__ int   g_cur[NN];
__device__ int   g_csrc[ET];

__device__ __forceinline__ float sigf(float x) { return 1.0f / (1.0f + __expf(-x)); }
__device__ __forceinline__ float lrelu(float e) { return (e > 0.f) ? e : 0.2f * e; }
__device__ __forceinline__ unsigned packbf(float a, float b) {
    __nv_bfloat162 t = __floats2bfloat162_rn(a, b);
    return *(unsigned*)&t;
}

// ---------------- CSR build ----------------------------------------------------
__global__ void k_degree(const int* __restrict__ ei, int E) {
    int i = blockIdx.x * blockDim.x + threadIdx.x;
    if (i >= E + NN) return;
    int dst = (i < E) ? ei[E + i] : (i - E);
    atomicAdd(&g_deg[dst], 1);
}

__global__ void k_scan() {
    __shared__ int sums[1024];
    const int CH = 20;
    int t = threadIdx.x;
    int b = t * CH;
    int e = min(b + CH, NN);
    int tmp[CH];
    int local = 0;
    for (int i = b; i < e; i++) { tmp[i - b] = g_deg[i]; local += tmp[i - b]; }
    sums[t] = local;
    __syncthreads();
    for (int o = 1; o < 1024; o <<= 1) {
        int v = (t >= o) ? sums[t - o] : 0;
        __syncthreads();
        sums[t] += v;
        __syncthreads();
    }
    int run = sums[t] - local;
    for (int i = b; i < e; i++) {
        g_offs[i] = run;
        g_cur[i]  = run;
        run += tmp[i - b];
    }
    if (b < NN && e == NN) g_offs[NN] = run;
}

__global__ void k_scatter(const int* __restrict__ ei, int E) {
    int i = blockIdx.x * blockDim.x + threadIdx.x;
    if (i >= E + NN) return;
    int src, dst;
    if (i < E) { src = ei[i]; dst = ei[E + i]; }
    else       { src = dst = i - E; }
    int pos = atomicAdd(&g_cur[dst], 1);
    g_csrc[pos] = src;
}

// ---------------- weight prep ----------------------------------------------------
__global__ void k_prepw(const float* __restrict__ W1, const float* __restrict__ Wih,
                        const float* __restrict__ W2) {
    int idx = blockIdx.x * blockDim.x + threadIdx.x;
    const int S0 = FIN * D1;
    const int S1 = G4 * D1;
    const int S2 = F2C * D1;
    if (idx < S0) {
        int r = idx / D1, c = idx % D1;
        g_W1b[(long)c * FIN + r] = __float2bfloat16(W1[idx]);
    } else if (idx < S0 + S1) {
        int i = idx - S0;
        g_Wihb[i] = __float2bfloat16(Wih[i]);
    } else if (idx < S0 + S1 + S2) {
        int i = idx - S0 - S1;
        int r = i / D1, c = i % D1;
        g_W2b[(long)c * F2C + r] = __float2bfloat16(W2[i]);
    }
}

__global__ void k_folds(const float* __restrict__ W1, const float* __restrict__ as1,
                        const float* __restrict__ ad1,
                        const float* __restrict__ W2, const float* __restrict__ as2,
                        const float* __restrict__ ad2) {
    int idx = blockIdx.x * blockDim.x + threadIdx.x;
    const int N1 = FIN * 16;
    const int N2 = F2C * 16;
    const float* W; const float* asv; const float* adv; float* V; int li;
    if (idx < N1) { W = W1; asv = as1; adv = ad1; V = g_v1; li = idx; }
    else if (idx < N1 + N2) { W = W2; asv = as2; adv = ad2; V = g_v2; li = idx - N1; }
    else return;
    int k = li >> 4;
    int col = li & 15;
    int h = col & 7;
    const float* att = (col & 8) ? adv : asv;
    float acc = 0.f;
#pragma unroll 8
    for (int f = 0; f < F2C; f++)
        acc += W[(long)k * D1 + h * F2C + f] * att[h * F2C + f];
    V[li] = acc;
}

// ---------------- attention logits layer 1 (from x) ------------------------------
template <int K>
__global__ __launch_bounds__(256) void k_attnx(const float* __restrict__ feat,
                                               const float* __restrict__ V) {
    __shared__ float sV[K * 17];
    int tid = threadIdx.x;
    for (int idx = tid; idx < K * 16; idx += 256) {
        int k = idx >> 4, c = idx & 15;
        sV[k * 17 + c] = V[idx];
    }
    __syncthreads();
    int warp = tid >> 5, lane = tid & 31;
    int n = blockIdx.x * 8 + warp;
    if (n >= NN) return;
    float xv[K / 32];
#pragma unroll
    for (int c = 0; c < K / 32; c++) xv[c] = feat[(long)n * K + c * 32 + lane];
    float acc[16];
#pragma unroll
    for (int h = 0; h < 16; h++) acc[h] = 0.f;
#pragma unroll
    for (int c = 0; c < K / 32; c++) {
        int k = c * 32 + lane;
#pragma unroll
        for (int h = 0; h < 16; h++) acc[h] += xv[c] * sV[k * 17 + h];
    }
#pragma unroll
    for (int off = 16; off > 0; off >>= 1)
#pragma unroll
        for (int h = 0; h < 16; h++)
            acc[h] += __shfl_xor_sync(0xffffffffu, acc[h], off);
    if (lane == 0) {
#pragma unroll
        for (int h = 0; h < 8; h++) {
            g_as[n * HC + h] = acc[h];
            g_ad[n * HC + h] = acc[8 + h];
        }
    }
}

// ---------------- fused aggregation (R15-proven, + node offset & logit ptrs) --------
template <typename TO, bool SMAX>
__global__ __launch_bounds__(128) void k_agg(int n0,
                                             const float* __restrict__ asv,
                                             const float* __restrict__ adv,
                                             const __nv_bfloat16* __restrict__ hsrc,
                                             const float* __restrict__ bias,
                                             TO* __restrict__ out) {
    __shared__ float sAl[32][9];
    __shared__ int   sSrc[32];
    __shared__ float sMx[8], sInv[8], sAd[8];
    __shared__ float red[128];
    int n = n0 + blockIdx.x;
    int t = threadIdx.x;
    int h = t >> 4, sub = t & 15;
    int beg = g_offs[n], end = g_offs[n + 1];
    int deg = end - beg;
    if (t < 8) sAd[t] = adv[n * HC + t];
    __syncthreads();

    float4 acc = make_float4(0.f, 0.f, 0.f, 0.f);
    float inv;

    if (deg <= 32) {
        int cnt = deg;
        for (int v = t; v < cnt * 8; v += 128) {
            int c = v >> 3, hh = v & 7;
            int src = g_csrc[beg + c];
            if (hh == 0) sSrc[c] = src;
            sAl[c][hh] = lrelu(asv[src * HC + hh] + sAd[hh]);
        }
        __syncthreads();
        float mx = -1e30f, s = 0.f;
        for (int c = sub; c < cnt; c += 16) {
            float e = sAl[c][h];
            float nm = fmaxf(mx, e);
            s = s * __expf(mx - nm) + __expf(e - nm);
            mx = nm;
        }
#pragma unroll
        for (int o = 8; o > 0; o >>= 1) {
            float mo = __shfl_xor_sync(0xffffffffu, mx, o, 16);
            float so = __shfl_xor_sync(0xffffffffu, s, o, 16);
            float nm = fmaxf(mx, mo);
            s = s * __expf(mx - nm) + so * __expf(mo - nm);
            mx = nm;
        }
        if (sub == 0) {
            sMx[h] = mx;
            sInv[h] = 1.0f / (s + 1e-16f);
        }
        __syncthreads();
        for (int v = t; v < cnt * 8; v += 128) {
            int c = v >> 3, hh = v & 7;
            sAl[c][hh] = __expf(sAl[c][hh] - sMx[hh]);
        }
        __syncthreads();
        inv = sInv[h];
        for (int c = 0; c < cnt; c++) {
            float alpha = sAl[c][h];
            int src = sSrc[c];
            uint2 u = *(const uint2*)&hsrc[(long)src * D1 + t * 4];
            float2 p0 = __bfloat1622float2(*(__nv_bfloat162*)&u.x);
            float2 p1 = __bfloat1622float2(*(__nv_bfloat162*)&u.y);
            acc.x += alpha * p0.x;
            acc.y += alpha * p0.y;
            acc.z += alpha * p1.x;
            acc.w += alpha * p1.y;
        }
    } else {
        float mx = -1e30f, s = 0.f;
        float adn = sAd[h];
        for (int j = beg + sub; j < end; j += 16) {
            float e = lrelu(asv[g_csrc[j] * HC + h] + adn);
            float nm = fmaxf(mx, e);
            s = s * __expf(mx - nm) + __expf(e - nm);
            mx = nm;
        }
#pragma unroll
        for (int o = 8; o > 0; o >>= 1) {
            float mo = __shfl_xor_sync(0xffffffffu, mx, o, 16);
            float so = __shfl_xor_sync(0xffffffffu, s, o, 16);
            float nm = fmaxf(mx, mo);
            s = s * __expf(mx - nm) + so * __expf(mo - nm);
            mx = nm;
        }
        if (sub == 0) {
            sMx[h] = mx;
            sInv[h] = 1.0f / (s + 1e-16f);
        }
        __syncthreads();
        inv = sInv[h];
        for (int c0 = beg; c0 < end; c0 += 32) {
            int cnt = min(32, end - c0);
            __syncthreads();
            for (int v = t; v < cnt * 8; v += 128) {
                int c = v >> 3, hh = v & 7;
                int src = g_csrc[c0 + c];
                if (hh == 0) sSrc[c] = src;
                float e = lrelu(asv[src * HC + hh] + sAd[hh]);
                sAl[c][hh] = __expf(e - sMx[hh]);
            }
            __syncthreads();
            for (int c = 0; c < cnt; c++) {
                float alpha = sAl[c][h];
                int src = sSrc[c];
                uint2 u = *(const uint2*)&hsrc[(long)src * D1 + t * 4];
                float2 p0 = __bfloat1622float2(*(__nv_bfloat162*)&u.x);
                float2 p1 = __bfloat1622float2(*(__nv_bfloat162*)&u.y);
                acc.x += alpha * p0.x;
                acc.y += alpha * p0.y;
                acc.z += alpha * p1.x;
                acc.w += alpha * p1.y;
            }
        }
    }

    float4 b = *(const float4*)&bias[t * 4];
    acc.x = acc.x * inv + b.x;
    acc.y = acc.y * inv + b.y;
    acc.z = acc.z * inv + b.z;
    acc.w = acc.w * inv + b.w;

    if (!SMAX) {
        if (sizeof(TO) == 2) {
            uint2 u = make_uint2(packbf(acc.x, acc.y), packbf(acc.z, acc.w));
            *(uint2*)&out[(long)n * D1 + t * 4] = u;
        } else {
            *(float4*)&((float*)out)[(long)n * D1 + t * 4] = acc;
        }
        return;
    }

    float lm = fmaxf(fmaxf(acc.x, acc.y), fmaxf(acc.z, acc.w));
    red[t] = lm;
    __syncthreads();
#pragma unroll
    for (int o = 64; o > 0; o >>= 1) {
        if (t < o) red[t] = fmaxf(red[t], red[t + o]);
        __syncthreads();
    }
    float gm = red[0];
    __syncthreads();
    float e0 = __expf(acc.x - gm), e1 = __expf(acc.y - gm);
    float e2 = __expf(acc.z - gm), e3 = __expf(acc.w - gm);
    red[t] = e0 + e1 + e2 + e3;
    __syncthreads();
#pragma unroll
    for (int o = 64; o > 0; o >>= 1) {
        if (t < o) red[t] += red[t + o];
        __syncthreads();
    }
    float rinv = 1.0f / red[0];
    float* fout = (float*)out;
    *(float4*)&fout[(long)n * D1 + t * 4] =
        make_float4(e0 * rinv, e1 * rinv, e2 * rinv, e3 * rinv);
}

// ---------------- bf16 TN GEMM: cp.async pipeline (R15-proven, SROW=36) -------------
#define SROW 36
#define ABYTES (128 * SROW * 4)
#define STAGEB (2 * ABYTES)
#define SMEMB  (2 * STAGEB)

template <typename TO>
__device__ __forceinline__ void storeC2(TO* C, long idx, float a, float b);
template <>
__device__ __forceinline__ void storeC2<float>(float* C, long idx, float a, float b) {
    *(float2*)&C[idx] = make_float2(a, b);
}
template <>
__device__ __forceinline__ void storeC2<__nv_bfloat16>(__nv_bfloat16* C, long idx, float a, float b) {
    unsigned u = packbf(a, b);
    *(unsigned*)&C[idx] = u;
}

__device__ __forceinline__ void ldsm4(unsigned& r0, unsigned& r1, unsigned& r2, unsigned& r3,
                                      unsigned addr) {
    asm volatile("ldmatrix.sync.aligned.m8n8.x4.shared.b16 {%0,%1,%2,%3}, [%4];"
                 : "=r"(r0), "=r"(r1), "=r"(r2), "=r"(r3) : "r"(addr));
}

__device__ __forceinline__ void cpasync16(unsigned dst, const void* src) {
    asm volatile("cp.async.cg.shared.global [%0], [%1], 16;" :: "r"(dst), "l"(src));
}

__device__ __forceinline__ void stsu4(unsigned addr, uint4 v) {
    asm volatile("st.shared.v4.b32 [%0], {%1,%2,%3,%4};"
                 :: "r"(addr), "r"(v.x), "r"(v.y), "r"(v.z), "r"(v.w));
}

template <typename TO, typename TI>
__global__ __launch_bounds__(256) void k_bgemm(int M, int N, int K,
                                               const TI* __restrict__ A,
                                               const __nv_bfloat16* __restrict__ Bt,
                                               TO* __restrict__ C) {
    constexpr bool CVTA = (sizeof(TI) == 4);
    extern __shared__ unsigned char smemRaw[];
    unsigned sBase = (unsigned)__cvta_generic_to_shared(smemRaw);
    int tid  = threadIdx.x;
    int lane = tid & 31;
    int warp = tid >> 5;
    int wr = warp & 3;
    int wc = warp >> 2;
    int blockRow = blockIdx.y * 128;
    int blockCol = blockIdx.x * 128;

    float acc[2][8][4];
#pragma unroll
    for (int i = 0; i < 2; i++)
#pragma unroll
        for (int j = 0; j < 8; j++)
#pragma unroll
            for (int q = 0; q < 4; q++) acc[i][j][q] = 0.0f;

    int sub = lane >> 3;
    int l7  = lane & 7;
    unsigned aOff[2];
#pragma unroll
    for (int i = 0; i < 2; i++) {
        int row = wr * 32 + i * 16 + (sub & 1) * 8 + l7;
        aOff[i] = row * (SROW * 4) + (sub >> 1) * 16;
    }
    unsigned bOff[4];
#pragma unroll
    for (int jj = 0; jj < 4; jj++) {
        int tile = jj * 2 + (sub >> 1);
        int row = wc * 64 + tile * 8 + l7;
        bOff[jj] = ABYTES + row * (SROW * 4) + (sub & 1) * 16;
    }

    int sr[2], sc[2], arow[2];
#pragma unroll
    for (int i = 0; i < 2; i++) {
        int idx = tid + i * 256;
        sr[i] = idx >> 2;
        sc[i] = idx & 3;
        arow[i] = min(blockRow + sr[i], M - 1);
    }

    int nk = K / 32;
    float4 fa[2][2], fan[2][2];

#pragma unroll
    for (int i = 0; i < 2; i++) {
        if (CVTA) {
            const float* af = (const float*)A;
            fa[i][0] = *(const float4*)&af[(long)arow[i] * K + sc[i] * 8];
            fa[i][1] = *(const float4*)&af[(long)arow[i] * K + sc[i] * 8 + 4];
        } else {
            unsigned dA = sBase + (sr[i] * SROW + sc[i] * 4) * 4;
            cpasync16(dA, &((const __nv_bfloat16*)A)[(long)arow[i] * K + sc[i] * 8]);
        }
        unsigned dB = sBase + ABYTES + (sr[i] * SROW + sc[i] * 4) * 4;
        cpasync16(dB, &Bt[(long)(blockCol + sr[i]) * K + sc[i] * 8]);
    }
    asm volatile("cp.async.commit_group;" ::: "memory");

    for (int it = 0; it < nk; it++) {
        int stage = it & 1;
        if (CVTA) {
#pragma unroll
            for (int i = 0; i < 2; i++) {
                uint4 u = make_uint4(packbf(fa[i][0].x, fa[i][0].y),
                                     packbf(fa[i][0].z, fa[i][0].w),
                                     packbf(fa[i][1].x, fa[i][1].y),
                                     packbf(fa[i][1].z, fa[i][1].w));
                stsu4(sBase + stage * STAGEB + (sr[i] * SROW + sc[i] * 4) * 4, u);
            }
        }
        if (it + 1 < nk) {
            int nst = (it + 1) & 1;
            int koff = (it + 1) * 32;
#pragma unroll
            for (int i = 0; i < 2; i++) {
                if (CVTA) {
                    const float* af = (const float*)A;
                    fan[i][0] = *(const float4*)&af[(long)arow[i] * K + koff + sc[i] * 8];
                    fan[i][1] = *(const float4*)&af[(long)arow[i] * K + koff + sc[i] * 8 + 4];
                } else {
                    unsigned dA = sBase + nst * STAGEB + (sr[i] * SROW + sc[i] * 4) * 4;
                    cpasync16(dA, &((const __nv_bfloat16*)A)[(long)arow[i] * K + koff + sc[i] * 8]);
                }
                unsigned dB = sBase + nst * STAGEB + ABYTES + (sr[i] * SROW + sc[i] * 4) * 4;
                cpasync16(dB, &Bt[(long)(blockCol + sr[i]) * K + koff + sc[i] * 8]);
            }
            asm volatile("cp.async.commit_group;" ::: "memory");
            asm volatile("cp.async.wait_group 1;" ::: "memory");
        } else {
            asm volatile("cp.async.wait_group 0;" ::: "memory");
        }
        __syncthreads();

        unsigned stBase = sBase + stage * STAGEB;
#pragma unroll
        for (int ks = 0; ks < 2; ks++) {
            unsigned kadd = ks * 32;
            unsigned a[2][4], b[8][2];
#pragma unroll
            for (int i = 0; i < 2; i++)
                ldsm4(a[i][0], a[i][1], a[i][2], a[i][3], stBase + aOff[i] + kadd);
#pragma unroll
            for (int jj = 0; jj < 4; jj++)
                ldsm4(b[jj * 2][0], b[jj * 2][1], b[jj * 2 + 1][0], b[jj * 2 + 1][1],
                      stBase + bOff[jj] + kadd);
#pragma unroll
            for (int i = 0; i < 2; i++) {
#pragma unroll
                for (int j = 0; j < 8; j++) {
                    asm volatile(
                        "mma.sync.aligned.m16n8k16.row.col.f32.bf16.bf16.f32 "
                        "{%0,%1,%2,%3}, {%4,%5,%6,%7}, {%8,%9}, {%0,%1,%2,%3};"
                        : "+f"(acc[i][j][0]), "+f"(acc[i][j][1]),
                          "+f"(acc[i][j][2]), "+f"(acc[i][j][3])
                        : "r"(a[i][0]), "r"(a[i][1]), "r"(a[i][2]), "r"(a[i][3]),
                          "r"(b[j][0]), "r"(b[j][1]));
                }
            }
        }
        if (CVTA) {
#pragma unroll
            for (int i = 0; i < 2; i++) {
                fa[i][0] = fan[i][0];
                fa[i][1] = fan[i][1];
            }
        }
        __syncthreads();
    }

#pragma unroll
    for (int i = 0; i < 2; i++) {
        int r = blockRow + wr * 32 + i * 16 + (lane >> 2);
#pragma unroll
        for (int j = 0; j < 8; j++) {
            int c = blockCol + wc * 64 + j * 8 + (lane & 3) * 2;
            if (r < M)
                storeC2<TO>(C, (long)r * N + c, acc[i][j][0], acc[i][j][1]);
            if (r + 8 < M)
                storeC2<TO>(C, (long)(r + 8) * N + c, acc[i][j][2], acc[i][j][3]);
        }
    }
}

// ---------------- LSTM + fused layer-2 attention logits (chunked) ---------------------
__global__ __launch_bounds__(256) void k_lstm(int n0, int nCnt,
                                              const float* __restrict__ b_ih,
                                              const float* __restrict__ b_hh,
                                              const float* __restrict__ V2) {
    __shared__ float sV[F2C * 17];
    __shared__ float sH[4][F2C];
    int t = threadIdx.x;
    for (int idx = t; idx < F2C * 16; idx += 256) {
        int k = idx >> 4, c = idx & 15;
        sV[k * 17 + c] = V2[idx];
    }
    int nb = n0 + blockIdx.x * 4 + (t >> 6);
    int j = t & 63;
    float r = 0.f;
    if (nb < n0 + nCnt) {
        const float* g = g_gates + (long)nb * G4;
        float i_ = g[j]       + b_ih[j]       + b_hh[j];
        float gg = g[128 + j] + b_ih[128 + j] + b_hh[128 + j];
        float o_ = g[192 + j] + b_ih[192 + j] + b_hh[192 + j];
        float c  = sigf(i_) * tanhf(gg);
        r = fmaxf(sigf(o_) * tanhf(c), 0.0f);
        g_h2b[(long)nb * F2C + j] = __float2bfloat16(r);
    }
    sH[t >> 6][j] = r;
    __syncthreads();
    int p = t >> 2, q = t & 3;
    int node = p >> 4, c = p & 15;
    float sum = 0.f;
#pragma unroll
    for (int k = 0; k < 16; k++)
        sum += sH[node][q * 16 + k] * sV[(q * 16 + k) * 17 + c];
    sum += __shfl_xor_sync(0xffffffffu, sum, 1, 4);
    sum += __shfl_xor_sync(0xffffffffu, sum, 2, 4);
    if (q == 0) {
        int n2 = n0 + blockIdx.x * 4 + node;
        if (n2 < n0 + nCnt) {
            if (c < 8) g_as2[n2 * HC + c] = sum;
            else       g_ad2[n2 * HC + c - 8] = sum;
        }
    }
}

// ---------------- launch ------------------------------------------------------------------
extern "C" void kernel_launch(void* const* d_in, const int* in_sizes, int n_in,
                              void* d_out, int out_size) {
    const float* x        = (const float*)d_in[0];
    const int*   ei       = (const int*)d_in[1];
    const float* W1       = (const float*)d_in[3];
    const float* att_src1 = (const float*)d_in[4];
    const float* att_dst1 = (const float*)d_in[5];
    const float* bias1    = (const float*)d_in[6];
    const float* W_ih     = (const float*)d_in[7];
    const float* b_ih     = (const float*)d_in[9];
    const float* b_hh     = (const float*)d_in[10];
    const float* W2       = (const float*)d_in[11];
    const float* att_src2 = (const float*)d_in[12];
    const float* att_dst2 = (const float*)d_in[13];
    const float* bias2    = (const float*)d_in[14];
    float* out = (float*)d_out;

    int E = in_sizes[1] / 2;
    int etot = E + NN;

    void* p_deg = nullptr;   cudaGetSymbolAddress(&p_deg, g_deg);
    void* p_v1 = nullptr;    cudaGetSymbolAddress(&p_v1, g_v1);
    void* p_v2 = nullptr;    cudaGetSymbolAddress(&p_v2, g_v2);
    void* p_W1b = nullptr;   cudaGetSymbolAddress(&p_W1b, g_W1b);
    void* p_Wihb = nullptr;  cudaGetSymbolAddress(&p_Wihb, g_Wihb);
    void* p_W2b = nullptr;   cudaGetSymbolAddress(&p_W2b, g_W2b);
    void* p_h1b = nullptr;   cudaGetSymbolAddress(&p_h1b, g_h1b);
    void* p_agg1b = nullptr; cudaGetSymbolAddress(&p_agg1b, g_agg1b);
    void* p_gates = nullptr; cudaGetSymbolAddress(&p_gates, g_gates);
    void* p_h2b = nullptr;   cudaGetSymbolAddress(&p_h2b, g_h2b);
    void* p_h3b = nullptr;   cudaGetSymbolAddress(&p_h3b, g_h3b);
    void* p_as = nullptr;    cudaGetSymbolAddress(&p_as, g_as);
    void* p_ad = nullptr;    cudaGetSymbolAddress(&p_ad, g_ad);
    void* p_as2 = nullptr;   cudaGetSymbolAddress(&p_as2, g_as2);
    void* p_ad2 = nullptr;   cudaGetSymbolAddress(&p_ad2, g_ad2);

    static bool s_init = false;
    static cudaStream_t s1, s2;
    static cudaEvent_t evFork, evCsr, evPrepW, evAtt1, evG1, evC1;
    if (!s_init) {
        cudaFuncSetAttribute(k_bgemm<__nv_bfloat16, float>,
                             cudaFuncAttributeMaxDynamicSharedMemorySize, SMEMB);
        cudaFuncSetAttribute(k_bgemm<__nv_bfloat16, __nv_bfloat16>,
                             cudaFuncAttributeMaxDynamicSharedMemorySize, SMEMB);
        cudaFuncSetAttribute(k_bgemm<float, __nv_bfloat16>,
                             cudaFuncAttributeMaxDynamicSharedMemorySize, SMEMB);
        cudaStreamCreateWithFlags(&s1, cudaStreamNonBlocking);
        cudaStreamCreateWithFlags(&s2, cudaStreamNonBlocking);
        cudaEventCreateWithFlags(&evFork, cudaEventDisableTiming);
        cudaEventCreateWithFlags(&evCsr, cudaEventDisableTiming);
        cudaEventCreateWithFlags(&evPrepW, cudaEventDisableTiming);
        cudaEventCreateWithFlags(&evAtt1, cudaEventDisableTiming);
        cudaEventCreateWithFlags(&evG1, cudaEventDisableTiming);
        cudaEventCreateWithFlags(&evC1, cudaEventDisableTiming);
        s_init = true;
    }

    const __nv_bfloat16* h1b = (const __nv_bfloat16*)p_h1b;
    const __nv_bfloat16* h2b = (const __nv_bfloat16*)p_h2b;
    const __nv_bfloat16* h3b = (const __nv_bfloat16*)p_h3b;
    __nv_bfloat16* agg1b = (__nv_bfloat16*)p_agg1b;
    float* gates = (float*)p_gates;

    // ---- fork ----
    cudaEventRecord(evFork, 0);
    cudaStreamWaitEvent(s1, evFork, 0);
    cudaStreamWaitEvent(s2, evFork, 0);

    // s1: CSR chain
    cudaMemsetAsync(p_deg, 0, NN * sizeof(int), s1);
    k_degree<<<(etot + 255) / 256, 256, 0, s1>>>(ei, E);
    k_scan<<<1, 1024, 0, s1>>>();
    k_scatter<<<(etot + 255) / 256, 256, 0, s1>>>(ei, E);
    cudaEventRecord(evCsr, s1);

    // s2: weight prep -> folds -> attnx1
    k_prepw<<<((FIN + G4 + F2C) * D1 + 255) / 256, 256, 0, s2>>>(W1, W_ih, W2);
    cudaEventRecord(evPrepW, s2);
    k_folds<<<((FIN + F2C) * 16 + 255) / 256, 256, 0, s2>>>(W1, att_src1, att_dst1,
                                                            W2, att_src2, att_dst2);
    k_attnx<FIN><<<2500, 256, 0, s2>>>(x, (const float*)p_v1);
    cudaEventRecord(evAtt1, s2);

    // default stream: GEMM1 (fp32 x converted in-kernel)
    cudaStreamWaitEvent(0, evPrepW, 0);
    {
        dim3 grid(D1 / 128, (NN + 127) / 128);
        k_bgemm<__nv_bfloat16, float><<<grid, 256, SMEMB>>>(NN, D1, FIN, x,
                                                            (const __nv_bfloat16*)p_W1b,
                                                            (__nv_bfloat16*)p_h1b);
    }
    cudaEventRecord(evG1, 0);
    cudaStreamWaitEvent(0, evCsr, 0);
    cudaStreamWaitEvent(0, evAtt1, 0);
    // s1 picks up chunk-1 chain after GEMM1 + attnx1 + its own CSR
    cudaStreamWaitEvent(s1, evG1, 0);
    cudaStreamWaitEvent(s1, evAtt1, 0);

    dim3 gridHalf(G4 / 128, (NHALF + 127) / 128);
    dim3 gridHalf3(D1 / 128, (NHALF + 127) / 128);

    // ---- chunk 0 chain (default stream) ----
    k_agg<__nv_bfloat16, false><<<NHALF, 128>>>(0, (const float*)p_as, (const float*)p_ad,
                                                h1b, bias1, agg1b);
    k_bgemm<float, __nv_bfloat16><<<gridHalf, 256, SMEMB>>>(NHALF, G4, D1,
                                                            (const __nv_bfloat16*)agg1b,
                                                            (const __nv_bfloat16*)p_Wihb,
                                                            gates);
    k_lstm<<<(NHALF + 3) / 4, 256>>>(0, NHALF, b_ih, b_hh, (const float*)p_v2);
    k_bgemm<__nv_bfloat16, __nv_bfloat16><<<gridHalf3, 256, SMEMB>>>(NHALF, D1, F2C,
                                                                     h2b,
                                                                     (const __nv_bfloat16*)p_W2b,
                                                                     (__nv_bfloat16*)p_h3b);

    // ---- chunk 1 chain (s1) ----
    k_agg<__nv_bfloat16, false><<<NHALF, 128, 0, s1>>>(NHALF, (const float*)p_as,
                                                       (const float*)p_ad,
                                                       h1b, bias1, agg1b);
    k_bgemm<float, __nv_bfloat16><<<gridHalf, 256, SMEMB, s1>>>(
        NHALF, G4, D1,
        (const __nv_bfloat16*)(agg1b + (long)NHALF * D1),
        (const __nv_bfloat16*)p_Wihb,
        gates + (long)NHALF * G4);
    k_lstm<<<(NHALF + 3) / 4, 256, 0, s1>>>(NHALF, NHALF, b_ih, b_hh, (const float*)p_v2);
    k_bgemm<__nv_bfloat16, __nv_bfloat16><<<gridHalf3, 256, SMEMB, s1>>>(
        NHALF, D1, F2C,
        h2b + (long)NHALF * F2C,
        (const __nv_bfloat16*)p_W2b,
        (__nv_bfloat16*)p_h3b + (long)NHALF * D1);
    cudaEventRecord(evC1, s1);

    // ---- join, final fused gather + bias2 + softmax ----
    cudaStreamWaitEvent(0, evC1, 0);
    k_agg<float, true><<<NN, 128>>>(0, (const float*)p_as2, (const float*)p_ad2,
                                    h3b, bias2, out);
}